// round 13
// baseline (speedup 1.0000x reference)
#include <cuda_runtime.h>
#include <cstdint>

// Problem constants (fixed by the dataset)
#define BATCH   128
#define IN_DIM  2048
#define HID     2048
#define OUT_DIM 512
#define TSTEPS  32
#define VDECAY  0.5f
#define VTH     0.5f
#define KCHUNK  512   // reference split-K chunk (bit-exact contract from R2)

#define TB (TSTEPS * BATCH)   // 4096 batched rows (= GEMM M)

// ---------------- device scratch (no allocations allowed) ----------------
__device__ __align__(256) float g_xtk[IN_DIM * TB];      // input spikes k-major [K][T*B]
__device__ __align__(256) float g_p0[4 * HID * TB];      // layer0 partials [z][n][m]
__device__ __align__(256) float g_s0T[HID * TB];         // layer0 spikes k-major [H][T*B]
__device__ __align__(256) float g_p1[4 * HID * TB];      // layer1 partials [z][n][m]
__device__ __align__(256) float g_s1T[HID * TB];         // layer1 spikes k-major
__device__ __align__(256) float g_po[4 * OUT_DIM * TB];  // out-layer partials [z][n][m]
__device__ __align__(256) float g_w0t[IN_DIM * HID];     // W0 transposed [k][n]
__device__ __align__(256) float g_w1t[HID * HID];        // W1 transposed [k][n]
__device__ __align__(256) float g_wot[HID * OUT_DIM];    // Wo transposed [k][n]

// packed f32x2 ops: two independent IEEE-RN operations per instruction ->
// per-element rounding identical to scalar chains (validated bit-exact in R8).
#define FMA2(accv, av, wv) \
    asm("fma.rn.f32x2 %0, %1, %2, %0;" : "+l"(accv) : "l"(av), "l"(wv))
#define DUP2(dst, fval) \
    asm("mov.b64 %0, {%1, %1};" : "=l"(dst) : "r"(__float_as_uint(fval)))
#define CP_ASYNC16(dst_u32, src_ptr) \
    asm volatile("cp.async.cg.shared.global [%0], [%1], 16;" :: "r"(dst_u32), "l"(src_ptr))
#define CP_COMMIT() asm volatile("cp.async.commit_group;" ::: "memory")
#define CP_WAIT0()  asm volatile("cp.async.wait_group 0;" ::: "memory")

__device__ __forceinline__ uint32_t smem_u32(const void* p) {
    return (uint32_t)__cvta_generic_to_shared(p);
}
__device__ __forceinline__ float lo2(unsigned long long v) {
    return __uint_as_float((uint32_t)(v & 0xFFFFFFFFull));
}
__device__ __forceinline__ float hi2(unsigned long long v) {
    return __uint_as_float((uint32_t)(v >> 32));
}

// ---------------- input transpose: sd [B][K][T] -> xtk [K][T*B] ----------------
// One block per k. Phase 1: coalesced reads over t. Phase 2: coalesced writes over b.
__global__ void xtrans_kernel(const float* __restrict__ sd) {
    __shared__ float tile[BATCH][TSTEPS + 1];   // [b][t], pad kills bank conflicts
    const int k = blockIdx.x;
    const int tid = threadIdx.x;                // 256 threads
    {
        int t  = tid & 31;
        int bg = tid >> 5;                      // 0..7
#pragma unroll
        for (int i = 0; i < 16; i++) {
            int b = bg + i * 8;
            tile[b][t] = sd[((size_t)b * IN_DIM + k) * TSTEPS + t];
        }
    }
    __syncthreads();
    {
        int b  = tid & 127;
        int tg = tid >> 7;                      // 0..1
#pragma unroll
        for (int i = 0; i < 16; i++) {
            int t = tg + i * 2;
            g_xtk[(size_t)k * TB + t * BATCH + b] = tile[b][t];
        }
    }
}

// ---------------- weight transpose: in[R][C] -> out[C][R] ----------------
template <int R, int C>
__global__ void wtrans_kernel(const float* __restrict__ in, float* __restrict__ out) {
    __shared__ float tile[32][33];
    int c0 = blockIdx.x * 32;
    int r0 = blockIdx.y * 32;
    int tx = threadIdx.x;
    int ty = threadIdx.y;
#pragma unroll
    for (int i = 0; i < 4; i++)
        tile[ty + i * 8][tx] = in[(size_t)(r0 + ty + i * 8) * C + c0 + tx];
    __syncthreads();
#pragma unroll
    for (int i = 0; i < 4; i++)
        out[(size_t)(c0 + ty + i * 8) * R + r0 + tx] = tile[tx][ty + i * 8];
}

// ---------------- LIF scan: fold 4 transposed partials, write spikes k-major ----------------
// g = ((p0+p1)+p2)+p3 left-assoc; v = (0.5*v*(1-s) + g) + bias ; s = (v > VTH).
// pin layout [z][n][t*B+b]; sall layout [n][t*B+b]. Threads: b fastest (8), n (32).
template <int N>
__global__ void lif_scan_kernel(const float* __restrict__ pin,
                                float* __restrict__ sall,
                                const float* __restrict__ v0in,   // [B][N]
                                const float* __restrict__ s0in,
                                const float* __restrict__ bias) {
    const int tid = threadIdx.x;
    const int b = blockIdx.y * 8 + (tid & 7);
    const int h = blockIdx.x * 32 + (tid >> 3);
    const size_t PL = (size_t)N * TB;
    float vv = v0in[(size_t)b * N + h];
    float ss = s0in[(size_t)b * N + h];
    float bb = bias[h];
    const size_t base = (size_t)h * TB + b;
#pragma unroll
    for (int t = 0; t < TSTEPS; t++) {
        size_t o = base + (size_t)t * BATCH;
        float g = __fadd_rn(__fadd_rn(__fadd_rn(pin[o], pin[PL + o]), pin[2 * PL + o]),
                            pin[3 * PL + o]);
        float decay = __fmul_rn(__fmul_rn(VDECAY, vv), __fadd_rn(1.0f, -ss));
        vv = __fadd_rn(__fadd_rn(decay, g), bb);
        ss = (vv > VTH) ? 1.0f : 0.0f;
        sall[o] = ss;
    }
}

// ---------------- output-layer LIF scan: fold partials + spike counts ----------------
__global__ void lifo_scan_kernel(const float* __restrict__ pin,   // [z][n][t*B+b]
                                 const float* __restrict__ v0in,  // [B][OUT]
                                 const float* __restrict__ s0in,
                                 const float* __restrict__ bias,
                                 float* __restrict__ out) {       // [B][OUT]
    const int tid = threadIdx.x;
    const int b = blockIdx.y * 8 + (tid & 7);
    const int n = blockIdx.x * 32 + (tid >> 3);
    const size_t PL = (size_t)OUT_DIM * TB;
    float vv = v0in[(size_t)b * OUT_DIM + n];
    float ss = s0in[(size_t)b * OUT_DIM + n];
    float bb = bias[n];
    float acc = 0.0f;
    const size_t base = (size_t)n * TB + b;
#pragma unroll
    for (int t = 0; t < TSTEPS; t++) {
        size_t o = base + (size_t)t * BATCH;
        float g = __fadd_rn(__fadd_rn(__fadd_rn(pin[o], pin[PL + o]), pin[2 * PL + o]),
                            pin[3 * PL + o]);
        float decay = __fmul_rn(__fmul_rn(VDECAY, vv), __fadd_rn(1.0f, -ss));
        vv = __fadd_rn(__fadd_rn(decay, g), bb);
        ss = (vv > VTH) ? 1.0f : 0.0f;
        acc += ss;
    }
    out[(size_t)b * OUT_DIM + n] = acc;
}

// ---------------- split-K chunk GEMM: all-cp.async, packed f32x2, TM8xTN8 ----------------
// Partial[z][n][m] = sum over k in chunk z of Xkm[k][m]*Wt[k][n], serial in-order
// FMA per element (bit-exact chunk chain). Both operands arrive via cp.async.
// BM=64 (m), BN=128 (n), 128 threads, thread tile 8x8. Epilogue stores C^T.
template <int N, int KTOT>
__global__ __launch_bounds__(128, 4) void gemm_kernel(
    const float* __restrict__ Xkm,     // [KTOT][TB] k-major
    const float* __restrict__ Wt,      // [KTOT][N] k-major
    float* __restrict__ part)          // [4][N][TB]
{
    constexpr int BK  = 16;
    constexpr int BM  = 64;
    constexpr int BN  = 128;
    constexpr int NT  = KCHUNK / BK;       // 32 tiles in this CTA's chunk
    constexpr int XPITCH = BM + 4;         // 68 floats
    constexpr int WPITCH = BN + 4;         // 132 floats

    __shared__ __align__(16) float Xs[2][BK][XPITCH];
    __shared__ __align__(16) float Ws[2][BK][WPITCH];

    const int tid = threadIdx.x;
    const int m0 = blockIdx.y * BM;
    const int n0 = blockIdx.x * BN;
    const int kbase = blockIdx.z * KCHUNK;

    // X cp.async mapping: 256 x 16B chunks per tile, 2 per thread.
    const int xrow0 = tid >> 4;            // rows xrow0, xrow0+8
    const int xc    = tid & 15;
    const float* Xp = Xkm + (size_t)(kbase + xrow0) * TB + m0 + xc * 4;

    // W cp.async mapping: 512 x 16B chunks per tile, 4 per thread.
    const int wrow0 = tid >> 5;            // rows wrow0, +4, +8, +12
    const int wc16  = tid & 31;
    const float* Wp = Wt + (size_t)(kbase + wrow0) * N + n0 + wc16 * 4;

    const int tx = tid % 16;
    const int ty = tid / 16;               // 0..7

    unsigned long long acc[8][4];
#pragma unroll
    for (int i = 0; i < 8; i++)
#pragma unroll
        for (int j = 0; j < 4; j++) acc[i][j] = 0ull;

    // prologue: tile0 X+W via cp.async
    {
        uint32_t xdst = smem_u32(&Xs[0][xrow0][xc * 4]);
        CP_ASYNC16(xdst, Xp);
        CP_ASYNC16(xdst + 8 * XPITCH * 4, Xp + (size_t)8 * TB);
        uint32_t wdst = smem_u32(&Ws[0][wrow0][wc16 * 4]);
#pragma unroll
        for (int i = 0; i < 4; i++)
            CP_ASYNC16(wdst + i * 4 * WPITCH * 4, Wp + (size_t)i * 4 * N);
        CP_COMMIT();
    }
    CP_WAIT0();
    __syncthreads();

    for (int t = 0; t < NT; t++) {
        const int cur = t & 1;
        const int nxt = cur ^ 1;
        if (t + 1 < NT) {
            // stage tile t+1 into the free buffers (in flight during compute)
            const float* xsrc = Xp + (size_t)(t + 1) * BK * TB;
            uint32_t xdst = smem_u32(&Xs[nxt][xrow0][xc * 4]);
            CP_ASYNC16(xdst, xsrc);
            CP_ASYNC16(xdst + 8 * XPITCH * 4, xsrc + (size_t)8 * TB);
            const float* wsrc = Wp + (size_t)(t + 1) * BK * N;
            uint32_t wdst = smem_u32(&Ws[nxt][wrow0][wc16 * 4]);
#pragma unroll
            for (int i = 0; i < 4; i++)
                CP_ASYNC16(wdst + i * 4 * WPITCH * 4, wsrc + (size_t)i * 4 * N);
            CP_COMMIT();
        }

#pragma unroll
        for (int kk = 0; kk < BK; kk++) {
            float4 xa = *reinterpret_cast<const float4*>(&Xs[cur][kk][ty * 4]);
            float4 xb = *reinterpret_cast<const float4*>(&Xs[cur][kk][32 + ty * 4]);
            ulonglong2 wA = *reinterpret_cast<const ulonglong2*>(&Ws[cur][kk][tx * 4]);
            ulonglong2 wB = *reinterpret_cast<const ulonglong2*>(&Ws[cur][kk][64 + tx * 4]);
            unsigned long long aa[8];
            DUP2(aa[0], xa.x); DUP2(aa[1], xa.y); DUP2(aa[2], xa.z); DUP2(aa[3], xa.w);
            DUP2(aa[4], xb.x); DUP2(aa[5], xb.y); DUP2(aa[6], xb.z); DUP2(aa[7], xb.w);
#pragma unroll
            for (int i = 0; i < 8; i++) {
                FMA2(acc[i][0], aa[i], wA.x);
                FMA2(acc[i][1], aa[i], wA.y);
                FMA2(acc[i][2], aa[i], wB.x);
                FMA2(acc[i][3], aa[i], wB.y);
            }
        }

        if (t + 1 < NT) CP_WAIT0();
        __syncthreads();
    }

    // epilogue: store C^T partials — part[z][n][m], m-quads from acc halves.
    float* base = part + (size_t)blockIdx.z * N * TB;
#pragma unroll
    for (int h = 0; h < 2; h++) {          // n groups: tx*4 / 64+tx*4
#pragma unroll
        for (int jj = 0; jj < 4; jj++) {
            const int pidx = 2 * h + (jj >> 1);
            const int hi_half = jj & 1;
            const int n = n0 + h * 64 + tx * 4 + jj;
            float4 f0, f1;
            if (hi_half) {
                f0.x = hi2(acc[0][pidx]); f0.y = hi2(acc[1][pidx]);
                f0.z = hi2(acc[2][pidx]); f0.w = hi2(acc[3][pidx]);
                f1.x = hi2(acc[4][pidx]); f1.y = hi2(acc[5][pidx]);
                f1.z = hi2(acc[6][pidx]); f1.w = hi2(acc[7][pidx]);
            } else {
                f0.x = lo2(acc[0][pidx]); f0.y = lo2(acc[1][pidx]);
                f0.z = lo2(acc[2][pidx]); f0.w = lo2(acc[3][pidx]);
                f1.x = lo2(acc[4][pidx]); f1.y = lo2(acc[5][pidx]);
                f1.z = lo2(acc[6][pidx]); f1.w = lo2(acc[7][pidx]);
            }
            float* col = base + (size_t)n * TB + m0;
            *reinterpret_cast<float4*>(col + ty * 4)      = f0;
            *reinterpret_cast<float4*>(col + 32 + ty * 4) = f1;
        }
    }
}

// ---------------- launcher ----------------
extern "C" void kernel_launch(void* const* d_in, const int* in_sizes, int n_in,
                              void* d_out, int out_size) {
    (void)in_sizes; (void)n_in; (void)out_size;
    const float* sd  = (const float*)d_in[0];
    const float* h0v = (const float*)d_in[1];
    const float* h0s = (const float*)d_in[2];
    const float* h1v = (const float*)d_in[3];
    const float* h1s = (const float*)d_in[4];
    const float* ov  = (const float*)d_in[5];
    const float* os  = (const float*)d_in[6];
    const float* W0  = (const float*)d_in[7];
    const float* b0  = (const float*)d_in[8];
    const float* W1  = (const float*)d_in[9];
    const float* b1  = (const float*)d_in[10];
    const float* Wo  = (const float*)d_in[11];
    const float* bo  = (const float*)d_in[12];
    float* out = (float*)d_out;

    float *xtk, *p0, *s0T, *p1, *s1T, *po, *w0t, *w1t, *wot;
    cudaGetSymbolAddress((void**)&xtk,  g_xtk);
    cudaGetSymbolAddress((void**)&p0,   g_p0);
    cudaGetSymbolAddress((void**)&s0T,  g_s0T);
    cudaGetSymbolAddress((void**)&p1,   g_p1);
    cudaGetSymbolAddress((void**)&s1T,  g_s1T);
    cudaGetSymbolAddress((void**)&po,   g_po);
    cudaGetSymbolAddress((void**)&w0t,  g_w0t);
    cudaGetSymbolAddress((void**)&w1t,  g_w1t);
    cudaGetSymbolAddress((void**)&wot,  g_wot);

    // 0) weight transposes (k-major for cp.async)
    {
        dim3 tb(32, 8);
        dim3 g0(IN_DIM / 32, HID / 32);
        wtrans_kernel<HID, IN_DIM><<<g0, tb>>>(W0, w0t);
        dim3 g1(HID / 32, HID / 32);
        wtrans_kernel<HID, HID><<<g1, tb>>>(W1, w1t);
        dim3 g2(HID / 32, OUT_DIM / 32);
        wtrans_kernel<OUT_DIM, HID><<<g2, tb>>>(Wo, wot);
    }

    // 1) input transpose: sd [B][K][T] -> xtk [K][T*B]
    xtrans_kernel<<<IN_DIM, 256>>>(sd);

    dim3 gridH(HID / 128, TB / 64, 4);       // (16, 64, 4) = 4096 CTAs
    dim3 gridO(OUT_DIM / 128, TB / 64, 4);   // (4, 64, 4)  = 1024 CTAs
    dim3 scanH(HID / 32, BATCH / 8);         // (64, 16)
    dim3 scanO(OUT_DIM / 32, BATCH / 8);     // (16, 16)

    // 2) layer0 GEMM
    gemm_kernel<HID, IN_DIM><<<gridH, 128>>>(xtk, w0t, p0);
    // 3) layer0 LIF scan (folds partials, writes spikes k-major)
    lif_scan_kernel<HID><<<scanH, 256>>>(p0, s0T, h0v, h0s, b0);
    // 4) layer1 GEMM
    gemm_kernel<HID, HID><<<gridH, 128>>>(s0T, w1t, p1);
    // 5) layer1 LIF scan
    lif_scan_kernel<HID><<<scanH, 256>>>(p1, s1T, h1v, h1s, b1);
    // 6) output-layer GEMM
    gemm_kernel<OUT_DIM, HID><<<gridO, 128>>>(s1T, wot, po);
    // 7) output LIF scan + spike-count accumulation
    lifo_scan_kernel<<<scanO, 256>>>(po, ov, os, bo, out);
}